// round 14
// baseline (speedup 1.0000x reference)
#include <cuda_runtime.h>
#include <cstdint>

#define BATCH 32768
#define HID   512
#define KTOT  1024
#define KT    32
#define STAGES 3
#define ROW_F 32                          // floats per smem row (no pad; XOR swizzle)
#define TILE_F (128 * ROW_F)              // 4096 floats = 16 KB per tile
#define STAGE_F (2 * TILE_F)              // A + B per stage = 32 KB
#define SMEM_BYTES (STAGES * STAGE_F * 4) // 3 stages = 98304 bytes
#define WELE (512 * 512)

// Scratch (device globals; no cudaMalloc allowed). Referenced directly from
// device code — no cudaGetSymbolAddress (illegal during graph capture).
__device__ float g_z [(size_t)BATCH * HID];
__device__ float g_rh[(size_t)BATCH * HID];   // stored pre-rounded to tf32
__device__ float g_wt[6 * WELE];              // Wz,Wr,Wh,Uz,Ur,Uh tf32(rna), natural layout

// ---------------- helpers ----------------
__device__ __forceinline__ void cp_async16(float* sdst, const float* gsrc) {
    uint32_t s;
    asm("{ .reg .u64 t; cvta.to.shared.u64 t, %1; cvt.u32.u64 %0, t; }"
        : "=r"(s) : "l"(sdst));
    asm volatile("cp.async.cg.shared.global [%0], [%1], 16;" :: "r"(s), "l"(gsrc));
}
__device__ __forceinline__ void cp_commit() {
    asm volatile("cp.async.commit_group;" ::: "memory");
}
template <int N>
__device__ __forceinline__ void cp_wait() {
    asm volatile("cp.async.wait_group %0;" :: "n"(N) : "memory");
}
__device__ __forceinline__ uint32_t f2tf(float f) {
    uint32_t u;
    asm("cvt.rna.tf32.f32 %0, %1;" : "=r"(u) : "f"(f));
    return u;
}
__device__ __forceinline__ void mma_tf32(float c[4], float a0, float a1, float a2,
                                         float a3, float b0, float b1) {
    asm volatile(
        "mma.sync.aligned.m16n8k8.row.col.f32.tf32.tf32.f32 "
        "{%0,%1,%2,%3}, {%4,%5,%6,%7}, {%8,%9}, {%0,%1,%2,%3};"
        : "+f"(c[0]), "+f"(c[1]), "+f"(c[2]), "+f"(c[3])
        : "r"(__float_as_uint(a0)), "r"(__float_as_uint(a1)),
          "r"(__float_as_uint(a2)), "r"(__float_as_uint(a3)),
          "r"(__float_as_uint(b0)), "r"(__float_as_uint(b1)));
}
__device__ __forceinline__ float sigmoidf_(float v) {
    return 1.0f / (1.0f + __expf(-v));
}
__device__ __forceinline__ float tanh_fast(float v) {
    return 2.0f / (1.0f + __expf(-2.0f * v)) - 1.0f;
}

// ---------------- weight pre-pass: fp32 -> tf32(rna), natural layout ----------------
__global__ void cvt_w_kernel(const float4* __restrict__ w0, const float4* __restrict__ w1,
                             const float4* __restrict__ w2, const float4* __restrict__ w3,
                             const float4* __restrict__ w4, const float4* __restrict__ w5,
                             int n4) {
    int i = blockIdx.x * blockDim.x + threadIdx.x;
    if (i >= n4) return;
    const int m = blockIdx.y;
    const float4* src = (m == 0) ? w0 : (m == 1) ? w1 : (m == 2) ? w2
                      : (m == 3) ? w3 : (m == 4) ? w4 : w5;
    float4 v = src[i];
    v.x = __uint_as_float(f2tf(v.x));
    v.y = __uint_as_float(f2tf(v.y));
    v.z = __uint_as_float(f2tf(v.z));
    v.w = __uint_as_float(f2tf(v.w));
    ((float4*)(g_wt + (size_t)m * WELE))[i] = v;
}

// MODE 0: z/r kernel  (A=[x|h] raw fp32, B from g_wt,  grid.x=8)
// MODE 1: h kernel    (A=[x|g_rh],       B from g_wt,  grid.x=4)
template <int MODE>
__global__ void __launch_bounds__(256, 2)
gru_gemm(const float* __restrict__ x, const float* __restrict__ h_orig,
         const float* __restrict__ W1b, const float* __restrict__ U1b,
         const float* __restrict__ W2b, const float* __restrict__ U2b,
         float* __restrict__ out, int out_copies)
{
    extern __shared__ float smem[];
    const int tid    = threadIdx.x;
    const int lane   = tid & 31;
    const int wid    = tid >> 5;
    const int warp_m = wid >> 1;   // 0..3  (32 rows each)
    const int warp_n = wid & 1;    // 0..1  (64 cols each)
    const int mtile  = blockIdx.y;
    const int ntile  = blockIdx.x;

    // g_wt layout: [0]=Wz [1]=Wr [2]=Wh [3]=Uz [4]=Ur [5]=Uh
    bool is_r = false;
    int nbase;
    const float *Bw, *Bu, *bb1, *bb2, *A2;
    if (MODE == 0) {
        is_r  = (ntile >= 4);
        nbase = (ntile & 3) * 128;
        Bw  = g_wt + (is_r ? 1 : 0) * WELE;
        Bu  = g_wt + (is_r ? 4 : 3) * WELE;
        bb1 = is_r ? W2b : W1b;
        bb2 = is_r ? U2b : U1b;
        A2  = h_orig;
    } else {
        nbase = ntile * 128;
        Bw  = g_wt + 2 * WELE;
        Bu  = g_wt + 5 * WELE;
        bb1 = W1b; bb2 = U1b;
        A2  = g_rh;
    }

    float acc[2][8][4];
    #pragma unroll
    for (int i = 0; i < 2; i++)
        #pragma unroll
        for (int j = 0; j < 8; j++)
            #pragma unroll
            for (int k = 0; k < 4; k++) acc[i][j][k] = 0.0f;

    // smem chunk placement: chunk c (16B) of row r at c ^ ((r&1)<<2)
    auto load_tile = [&](int kt) {
        const int stage = kt % STAGES;
        const int kcol0 = kt * KT;
        const float* asrc = (kcol0 < 512) ? x  : A2;
        const float* bsrc = (kcol0 < 512) ? Bw : Bu;
        const int koff = kcol0 & 511;
        float* a = smem + stage * STAGE_F;
        float* b = a + TILE_F;
        #pragma unroll
        for (int i = 0; i < 4; i++) {
            int idx = tid + i * 256;        // 0..1023
            int r = idx >> 3;               // 0..127
            int c = idx & 7;                // chunk 0..7
            int sc = c ^ ((r & 1) << 2);    // parity XOR swizzle
            cp_async16(a + r * ROW_F + sc * 4,
                       asrc + (size_t)(mtile * 128 + r) * 512 + koff + c * 4);
            cp_async16(b + r * ROW_F + sc * 4,
                       bsrc + (size_t)(nbase + r) * 512 + koff + c * 4);
        }
    };

    auto compute = [&](int stage) {
        const float* a = smem + stage * STAGE_F + warp_m * 32 * ROW_F;
        const float* b = smem + stage * STAGE_F + TILE_F + warp_n * 64 * ROW_F;
        const int r = lane >> 2, t = lane & 3;
        const int par = (r & 1) << 2;       // row parity bit (same for r, r+8, r+16, ...)
        #pragma unroll
        for (int g = 0; g < 2; g++) {       // two 16-col groups per ktile
            const int sc = ((g << 2) + t) ^ par;
            const float* ap = a + r * ROW_F + sc * 4;
            const float* bp = b + r * ROW_F + sc * 4;
            // A quads: rows r, r+8 (mt=0) and r+16, r+24 (mt=1), all same parity
            float4 aq[2][2];
            aq[0][0] = *(const float4*)(ap);
            aq[0][1] = *(const float4*)(ap + 8 * ROW_F);
            aq[1][0] = *(const float4*)(ap + 16 * ROW_F);
            aq[1][1] = *(const float4*)(ap + 24 * ROW_F);
            #pragma unroll
            for (int nt = 0; nt < 8; nt++) {
                float4 bq = *(const float4*)(bp + nt * 8 * ROW_F);
                const float* bf = (const float*)&bq;
                #pragma unroll
                for (int h = 0; h < 2; h++) {
                    #pragma unroll
                    for (int mt = 0; mt < 2; mt++) {
                        const float* a0 = (const float*)&aq[mt][0];
                        const float* a1 = (const float*)&aq[mt][1];
                        mma_tf32(acc[mt][nt],
                                 a0[2 * h], a1[2 * h], a0[2 * h + 1], a1[2 * h + 1],
                                 bf[2 * h], bf[2 * h + 1]);
                    }
                }
            }
        }
    };

    // ---- 3-stage pipeline, ONE barrier per k-tile (R8 skeleton) ----
    load_tile(0); cp_commit();
    load_tile(1); cp_commit();
    const int NTILES = KTOT / KT;   // 32
    #pragma unroll 1
    for (int kt = 0; kt < NTILES; kt++) {
        if (kt < NTILES - 1) cp_wait<1>();
        else                 cp_wait<0>();
        __syncthreads();
        if (kt + 2 < NTILES) {        // safe: slot (kt+2)%3 == (kt-1)%3
            load_tile(kt + 2);
            cp_commit();
        }
        compute(kt % STAGES);
    }

    // ---- epilogue ----
    #pragma unroll
    for (int mt = 0; mt < 2; mt++) {
        #pragma unroll
        for (int rr = 0; rr < 2; rr++) {
            int row = mtile * 128 + warp_m * 32 + mt * 16 + (lane >> 2) + rr * 8;
            #pragma unroll
            for (int nt = 0; nt < 8; nt++) {
                int f = nbase + warp_n * 64 + nt * 8 + (lane & 3) * 2;  // 0..511
                float v0 = acc[mt][nt][rr * 2 + 0] + bb1[f]     + bb2[f];
                float v1 = acc[mt][nt][rr * 2 + 1] + bb1[f + 1] + bb2[f + 1];
                size_t o = (size_t)row * HID + f;
                if (MODE == 0) {
                    float s0 = sigmoidf_(v0);
                    float s1 = sigmoidf_(v1);
                    if (!is_r) {
                        *(float2*)(g_z + o) = make_float2(s0, s1);
                    } else {
                        float2 hh = *(const float2*)(h_orig + o);
                        float r0 = __uint_as_float(f2tf(s0 * hh.x));
                        float r1 = __uint_as_float(f2tf(s1 * hh.y));
                        *(float2*)(g_rh + o) = make_float2(r0, r1);
                    }
                } else {
                    float t0 = tanh_fast(v0);
                    float t1 = tanh_fast(v1);
                    float2 hh = *(const float2*)(h_orig + o);
                    float2 zz = *(const float2*)(g_z + o);
                    float hn0 = hh.x + zz.x * (t0 - hh.x);
                    float hn1 = hh.y + zz.y * (t1 - hh.y);
                    *(float2*)(out + o) = make_float2(hn0, hn1);
                    if (out_copies > 1)
                        *(float2*)(out + (size_t)BATCH * HID + o) = make_float2(hn0, hn1);
                }
            }
        }
    }
}

extern "C" void kernel_launch(void* const* d_in, const int* in_sizes, int n_in,
                              void* d_out, int out_size) {
    const float* x    = (const float*)d_in[0];
    const float* h    = (const float*)d_in[1];
    const float* Wz_w = (const float*)d_in[2];
    const float* Wz_b = (const float*)d_in[3];
    const float* Wr_w = (const float*)d_in[4];
    const float* Wr_b = (const float*)d_in[5];
    const float* Wh_w = (const float*)d_in[6];
    const float* Wh_b = (const float*)d_in[7];
    const float* Uz_w = (const float*)d_in[8];
    const float* Uz_b = (const float*)d_in[9];
    const float* Ur_w = (const float*)d_in[10];
    const float* Ur_b = (const float*)d_in[11];
    const float* Uh_w = (const float*)d_in[12];
    const float* Uh_b = (const float*)d_in[13];
    float* out = (float*)d_out;
    int copies = out_size / (BATCH * HID);

    cudaFuncSetAttribute(gru_gemm<0>, cudaFuncAttributeMaxDynamicSharedMemorySize, SMEM_BYTES);
    cudaFuncSetAttribute(gru_gemm<1>, cudaFuncAttributeMaxDynamicSharedMemorySize, SMEM_BYTES);

    // weight pre-pass (tf32 rna rounding only, natural layout), ~6 µs
    const int n4_w = WELE / 4;   // 65536
    dim3 cg(n4_w / 256, 6);
    cvt_w_kernel<<<cg, 256>>>((const float4*)Wz_w, (const float4*)Wr_w,
                              (const float4*)Wh_w, (const float4*)Uz_w,
                              (const float4*)Ur_w, (const float4*)Uh_w, n4_w);

    dim3 blk(256);
    dim3 g1(8, BATCH / 128);   // 4 z-tiles + 4 r-tiles
    dim3 g2(4, BATCH / 128);
    gru_gemm<0><<<g1, blk, SMEM_BYTES>>>(x, h, Wz_b, Uz_b, Wr_b, Ur_b, nullptr, 0);
    gru_gemm<1><<<g2, blk, SMEM_BYTES>>>(x, h, Wh_b, Uh_b, nullptr, nullptr, out, copies);
}

// round 15
// speedup vs baseline: 1.0021x; 1.0021x over previous
#include <cuda_runtime.h>
#include <cstdint>

#define BATCH 32768
#define HID   512
#define KTOT  1024
#define KT    32
#define STAGES 3
#define ROW_F 32                          // floats per smem row (no pad; XOR swizzle)
#define TILE_F (128 * ROW_F)              // 4096 floats = 16 KB per tile
#define STAGE_F (2 * TILE_F)              // A + B per stage = 32 KB
#define SMEM_BYTES (STAGES * STAGE_F * 4) // 3 stages = 98304 bytes
#define WELE (512 * 512)

// Scratch (device globals; no cudaMalloc allowed). Referenced directly from
// device code — no cudaGetSymbolAddress (illegal during graph capture).
__device__ float g_z [(size_t)BATCH * HID];
__device__ float g_rh[(size_t)BATCH * HID];   // stored pre-rounded to tf32
__device__ float g_wt[6 * WELE];              // Wz,Wr,Wh,Uz,Ur,Uh tf32(rna), natural layout

// ---------------- helpers ----------------
__device__ __forceinline__ void cp_async16(float* sdst, const float* gsrc) {
    uint32_t s;
    asm("{ .reg .u64 t; cvta.to.shared.u64 t, %1; cvt.u32.u64 %0, t; }"
        : "=r"(s) : "l"(sdst));
    asm volatile("cp.async.cg.shared.global [%0], [%1], 16;" :: "r"(s), "l"(gsrc));
}
__device__ __forceinline__ void cp_commit() {
    asm volatile("cp.async.commit_group;" ::: "memory");
}
template <int N>
__device__ __forceinline__ void cp_wait() {
    asm volatile("cp.async.wait_group %0;" :: "n"(N) : "memory");
}
__device__ __forceinline__ uint32_t f2tf(float f) {
    uint32_t u;
    asm("cvt.rna.tf32.f32 %0, %1;" : "=r"(u) : "f"(f));
    return u;
}
__device__ __forceinline__ void mma_tf32(float c[4], float a0, float a1, float a2,
                                         float a3, float b0, float b1) {
    asm volatile(
        "mma.sync.aligned.m16n8k8.row.col.f32.tf32.tf32.f32 "
        "{%0,%1,%2,%3}, {%4,%5,%6,%7}, {%8,%9}, {%0,%1,%2,%3};"
        : "+f"(c[0]), "+f"(c[1]), "+f"(c[2]), "+f"(c[3])
        : "r"(__float_as_uint(a0)), "r"(__float_as_uint(a1)),
          "r"(__float_as_uint(a2)), "r"(__float_as_uint(a3)),
          "r"(__float_as_uint(b0)), "r"(__float_as_uint(b1)));
}
__device__ __forceinline__ float sigmoidf_(float v) {
    return 1.0f / (1.0f + __expf(-v));
}
__device__ __forceinline__ float tanh_fast(float v) {
    return 2.0f / (1.0f + __expf(-2.0f * v)) - 1.0f;
}

// ---------------- weight pre-pass: fp32 -> tf32(rna), natural layout ----------------
__global__ void cvt_w_kernel(const float4* __restrict__ w0, const float4* __restrict__ w1,
                             const float4* __restrict__ w2, const float4* __restrict__ w3,
                             const float4* __restrict__ w4, const float4* __restrict__ w5,
                             int n4) {
    int i = blockIdx.x * blockDim.x + threadIdx.x;
    if (i >= n4) return;
    const int m = blockIdx.y;
    const float4* src = (m == 0) ? w0 : (m == 1) ? w1 : (m == 2) ? w2
                      : (m == 3) ? w3 : (m == 4) ? w4 : w5;
    float4 v = src[i];
    v.x = __uint_as_float(f2tf(v.x));
    v.y = __uint_as_float(f2tf(v.y));
    v.z = __uint_as_float(f2tf(v.z));
    v.w = __uint_as_float(f2tf(v.w));
    ((float4*)(g_wt + (size_t)m * WELE))[i] = v;
}

// MODE 0: z/r kernel  (A=[x|h] raw fp32, B from g_wt,  grid.x=8)
// MODE 1: h kernel    (A=[x|g_rh],       B from g_wt,  grid.x=4)
template <int MODE>
__global__ void __launch_bounds__(256, 2)
gru_gemm(const float* __restrict__ x, const float* __restrict__ h_orig,
         const float* __restrict__ W1b, const float* __restrict__ U1b,
         const float* __restrict__ W2b, const float* __restrict__ U2b,
         float* __restrict__ out, int out_copies)
{
    extern __shared__ float smem[];
    const int tid    = threadIdx.x;
    const int lane   = tid & 31;
    const int wid    = tid >> 5;
    const int warp_m = wid >> 1;   // 0..3  (32 rows each)
    const int warp_n = wid & 1;    // 0..1  (64 cols each)
    const int mtile  = blockIdx.y;
    const int ntile  = blockIdx.x;

    // g_wt layout: [0]=Wz [1]=Wr [2]=Wh [3]=Uz [4]=Ur [5]=Uh
    bool is_r = false;
    int nbase;
    const float *Bw, *Bu, *bb1, *bb2, *A2;
    if (MODE == 0) {
        is_r  = (ntile >= 4);
        nbase = (ntile & 3) * 128;
        Bw  = g_wt + (is_r ? 1 : 0) * WELE;
        Bu  = g_wt + (is_r ? 4 : 3) * WELE;
        bb1 = is_r ? W2b : W1b;
        bb2 = is_r ? U2b : U1b;
        A2  = h_orig;
    } else {
        nbase = ntile * 128;
        Bw  = g_wt + 2 * WELE;
        Bu  = g_wt + 5 * WELE;
        bb1 = W1b; bb2 = U1b;
        A2  = g_rh;
    }

    float acc[2][8][4];
    #pragma unroll
    for (int i = 0; i < 2; i++)
        #pragma unroll
        for (int j = 0; j < 8; j++)
            #pragma unroll
            for (int k = 0; k < 4; k++) acc[i][j][k] = 0.0f;

    // smem chunk placement: chunk c (16B) of row r at c ^ ((r&1)<<2)
    auto load_tile = [&](int kt) {
        const int stage = kt % STAGES;
        const int kcol0 = kt * KT;
        const float* asrc = (kcol0 < 512) ? x  : A2;
        const float* bsrc = (kcol0 < 512) ? Bw : Bu;
        const int koff = kcol0 & 511;
        float* a = smem + stage * STAGE_F;
        float* b = a + TILE_F;
        #pragma unroll
        for (int i = 0; i < 4; i++) {
            int idx = tid + i * 256;        // 0..1023
            int r = idx >> 3;               // 0..127
            int c = idx & 7;                // chunk 0..7
            int sc = c ^ ((r & 1) << 2);    // parity XOR swizzle
            cp_async16(a + r * ROW_F + sc * 4,
                       asrc + (size_t)(mtile * 128 + r) * 512 + koff + c * 4);
            cp_async16(b + r * ROW_F + sc * 4,
                       bsrc + (size_t)(nbase + r) * 512 + koff + c * 4);
        }
    };

    auto compute = [&](int stage) {
        const float* a = smem + stage * STAGE_F + warp_m * 32 * ROW_F;
        const float* b = smem + stage * STAGE_F + TILE_F + warp_n * 64 * ROW_F;
        const int r = lane >> 2, t = lane & 3;
        const int par = (r & 1) << 2;       // row parity bit (same for r, r+8, r+16, ...)
        #pragma unroll
        for (int g = 0; g < 2; g++) {       // two 16-col groups per ktile
            const int sc = ((g << 2) + t) ^ par;
            const float* ap = a + r * ROW_F + sc * 4;
            const float* bp = b + r * ROW_F + sc * 4;
            // A quads: rows r, r+8 (mt=0) and r+16, r+24 (mt=1), all same parity
            float4 aq[2][2];
            aq[0][0] = *(const float4*)(ap);
            aq[0][1] = *(const float4*)(ap + 8 * ROW_F);
            aq[1][0] = *(const float4*)(ap + 16 * ROW_F);
            aq[1][1] = *(const float4*)(ap + 24 * ROW_F);
            #pragma unroll
            for (int nt = 0; nt < 8; nt++) {
                float4 bq = *(const float4*)(bp + nt * 8 * ROW_F);
                const float* bf = (const float*)&bq;
                #pragma unroll
                for (int h = 0; h < 2; h++) {
                    #pragma unroll
                    for (int mt = 0; mt < 2; mt++) {
                        const float* a0 = (const float*)&aq[mt][0];
                        const float* a1 = (const float*)&aq[mt][1];
                        mma_tf32(acc[mt][nt],
                                 a0[2 * h], a1[2 * h], a0[2 * h + 1], a1[2 * h + 1],
                                 bf[2 * h], bf[2 * h + 1]);
                    }
                }
            }
        }
    };

    // ---- 3-stage pipeline, ONE barrier per k-tile (R8 skeleton) ----
    load_tile(0); cp_commit();
    load_tile(1); cp_commit();
    const int NTILES = KTOT / KT;   // 32
    #pragma unroll 1
    for (int kt = 0; kt < NTILES; kt++) {
        if (kt < NTILES - 1) cp_wait<1>();
        else                 cp_wait<0>();
        __syncthreads();
        if (kt + 2 < NTILES) {        // safe: slot (kt+2)%3 == (kt-1)%3
            load_tile(kt + 2);
            cp_commit();
        }
        compute(kt % STAGES);
    }

    // ---- epilogue ----
    #pragma unroll
    for (int mt = 0; mt < 2; mt++) {
        #pragma unroll
        for (int rr = 0; rr < 2; rr++) {
            int row = mtile * 128 + warp_m * 32 + mt * 16 + (lane >> 2) + rr * 8;
            #pragma unroll
            for (int nt = 0; nt < 8; nt++) {
                int f = nbase + warp_n * 64 + nt * 8 + (lane & 3) * 2;  // 0..511
                float v0 = acc[mt][nt][rr * 2 + 0] + bb1[f]     + bb2[f];
                float v1 = acc[mt][nt][rr * 2 + 1] + bb1[f + 1] + bb2[f + 1];
                size_t o = (size_t)row * HID + f;
                if (MODE == 0) {
                    float s0 = sigmoidf_(v0);
                    float s1 = sigmoidf_(v1);
                    if (!is_r) {
                        *(float2*)(g_z + o) = make_float2(s0, s1);
                    } else {
                        float2 hh = *(const float2*)(h_orig + o);
                        float r0 = __uint_as_float(f2tf(s0 * hh.x));
                        float r1 = __uint_as_float(f2tf(s1 * hh.y));
                        *(float2*)(g_rh + o) = make_float2(r0, r1);
                    }
                } else {
                    float t0 = tanh_fast(v0);
                    float t1 = tanh_fast(v1);
                    float2 hh = *(const float2*)(h_orig + o);
                    float2 zz = *(const float2*)(g_z + o);
                    float hn0 = hh.x + zz.x * (t0 - hh.x);
                    float hn1 = hh.y + zz.y * (t1 - hh.y);
                    *(float2*)(out + o) = make_float2(hn0, hn1);
                    if (out_copies > 1)
                        *(float2*)(out + (size_t)BATCH * HID + o) = make_float2(hn0, hn1);
                }
            }
        }
    }
}

extern "C" void kernel_launch(void* const* d_in, const int* in_sizes, int n_in,
                              void* d_out, int out_size) {
    const float* x    = (const float*)d_in[0];
    const float* h    = (const float*)d_in[1];
    const float* Wz_w = (const float*)d_in[2];
    const float* Wz_b = (const float*)d_in[3];
    const float* Wr_w = (const float*)d_in[4];
    const float* Wr_b = (const float*)d_in[5];
    const float* Wh_w = (const float*)d_in[6];
    const float* Wh_b = (const float*)d_in[7];
    const float* Uz_w = (const float*)d_in[8];
    const float* Uz_b = (const float*)d_in[9];
    const float* Ur_w = (const float*)d_in[10];
    const float* Ur_b = (const float*)d_in[11];
    const float* Uh_w = (const float*)d_in[12];
    const float* Uh_b = (const float*)d_in[13];
    float* out = (float*)d_out;
    int copies = out_size / (BATCH * HID);

    cudaFuncSetAttribute(gru_gemm<0>, cudaFuncAttributeMaxDynamicSharedMemorySize, SMEM_BYTES);
    cudaFuncSetAttribute(gru_gemm<1>, cudaFuncAttributeMaxDynamicSharedMemorySize, SMEM_BYTES);

    // weight pre-pass (tf32 rna rounding only, natural layout), ~6 µs
    const int n4_w = WELE / 4;   // 65536
    dim3 cg(n4_w / 256, 6);
    cvt_w_kernel<<<cg, 256>>>((const float4*)Wz_w, (const float4*)Wr_w,
                              (const float4*)Wh_w, (const float4*)Uz_w,
                              (const float4*)Ur_w, (const float4*)Uh_w, n4_w);

    dim3 blk(256);
    dim3 g1(8, BATCH / 128);   // 4 z-tiles + 4 r-tiles
    dim3 g2(4, BATCH / 128);
    gru_gemm<0><<<g1, blk, SMEM_BYTES>>>(x, h, Wz_b, Uz_b, Wr_b, Ur_b, nullptr, 0);
    gru_gemm<1><<<g2, blk, SMEM_BYTES>>>(x, h, Wh_b, Uh_b, nullptr, nullptr, out, copies);
}